// round 2
// baseline (speedup 1.0000x reference)
#include <cuda_runtime.h>

#define NB 128
#define NT 784
#define NH 256
#define NL 20
#define NC 10
#define REG_K 192
#define SMEM_K 64
#define WS_STRIDE 68

__device__ float g_xp[(size_t)NB * NT * NH];
__device__ float g_y [(size_t)NB * NT * NH];

static const int SMEM_SCAN_BYTES = (NH * WS_STRIDE + 2 * NH) * 4;
static const int SMEM_PROJ_BYTES = (NH * WS_STRIDE + 4 * NH) * 4;

__device__ __forceinline__ void ffma2(unsigned long long &d,
                                      unsigned long long a,
                                      unsigned long long b) {
    asm("fma.rn.f32x2 %0, %1, %2, %0;" : "+l"(d) : "l"(a), "l"(b));
}
__device__ __forceinline__ float hsum2(unsigned long long a) {
    unsigned int lo, hi;
    asm("mov.b64 {%0, %1}, %2;" : "=r"(lo), "=r"(hi) : "l"(a));
    return __uint_as_float(lo) + __uint_as_float(hi);
}

// layer-0 projection: I=1 -> xp = x*W_ih0[h] + b_ih0[h] + b_hh0[h]
__global__ void k_proj0(const float* __restrict__ x,
                        const float* __restrict__ w0,
                        const float* __restrict__ bi0,
                        const float* __restrict__ bh0) {
    int idx = blockIdx.x * 256 + threadIdx.x;
    int h  = idx & (NH - 1);
    int bt = idx >> 8;
    g_xp[idx] = x[bt] * w0[h] + bi0[h] + bh0[h];
}

// recurrence: one CTA per sample, h_t = relu(xp_t + W_hh h_{t-1})
__global__ __launch_bounds__(256, 1)
void k_scan(const float* __restrict__ Whh) {
    extern __shared__ float smem[];
    float* Ws   = smem;                   // [NH][WS_STRIDE]
    float* hbuf = smem + NH * WS_STRIDE;  // [2][NH]
    const int tid = threadIdx.x;
    const int b   = blockIdx.x;

    unsigned long long wreg2[REG_K / 2];
    {
        const ulonglong2* wrow =
            reinterpret_cast<const ulonglong2*>(Whh + (size_t)tid * NH);
        #pragma unroll
        for (int j = 0; j < REG_K / 4; j++) {
            ulonglong2 v = wrow[j];
            wreg2[2 * j] = v.x; wreg2[2 * j + 1] = v.y;
        }
    }
    for (int i = tid; i < NH * SMEM_K; i += 256) {
        int row = i >> 6, col = i & (SMEM_K - 1);
        Ws[row * WS_STRIDE + col] = Whh[row * NH + REG_K + col];
    }
    hbuf[tid] = 0.0f; hbuf[NH + tid] = 0.0f;
    __syncthreads();

    const float* xprow = g_xp + (size_t)b * NT * NH + tid;
    float*       yrow  = g_y  + (size_t)b * NT * NH + tid;
    const ulonglong2* wsl =
        reinterpret_cast<const ulonglong2*>(Ws + tid * WS_STRIDE);

    float xv = xprow[0];
    int cur = 0;
    for (int t = 0; t < NT; t++) {
        float xnext = (t + 1 < NT) ? xprow[(t + 1) * NH] : 0.0f;
        const ulonglong2* hc =
            reinterpret_cast<const ulonglong2*>(hbuf + cur * NH);
        unsigned long long a0 = 0, a1 = 0, a2 = 0, a3 = 0;
        #pragma unroll
        for (int j = 0; j < REG_K / 8; j++) {
            ulonglong2 h0 = hc[2 * j];
            ffma2(a0, wreg2[4 * j + 0], h0.x);
            ffma2(a1, wreg2[4 * j + 1], h0.y);
            ulonglong2 h1 = hc[2 * j + 1];
            ffma2(a2, wreg2[4 * j + 2], h1.x);
            ffma2(a3, wreg2[4 * j + 3], h1.y);
        }
        #pragma unroll
        for (int c = 0; c < SMEM_K / 4; c++) {
            ulonglong2 wv = wsl[c];
            ulonglong2 hv = hc[REG_K / 4 + c];
            ffma2(a0, wv.x, hv.x);
            ffma2(a1, wv.y, hv.y);
        }
        float s = (hsum2(a0) + hsum2(a1)) + (hsum2(a2) + hsum2(a3));
        float v = fmaxf(s + xv, 0.0f);
        int nxt = cur ^ 1;
        hbuf[nxt * NH + tid] = v;
        yrow[t * NH] = v;
        xv = xnext; cur = nxt;
        __syncthreads();
    }
}

// projection for layers 1..L-1: xp[r,h] = Y[r,:].W_ih[h,:] + b_ih[h]+b_hh_next[h]
__global__ __launch_bounds__(256, 1)
void k_proj(const float* __restrict__ Wih,
            const float* __restrict__ b1,
            const float* __restrict__ b2) {
    extern __shared__ float smem[];
    float* Ws = smem;
    float* rs = smem + NH * WS_STRIDE;   // [4][NH]
    const int tid = threadIdx.x;

    unsigned long long wreg2[REG_K / 2];
    {
        const ulonglong2* wrow =
            reinterpret_cast<const ulonglong2*>(Wih + (size_t)tid * NH);
        #pragma unroll
        for (int j = 0; j < REG_K / 4; j++) {
            ulonglong2 v = wrow[j];
            wreg2[2 * j] = v.x; wreg2[2 * j + 1] = v.y;
        }
    }
    for (int i = tid; i < NH * SMEM_K; i += 256) {
        int row = i >> 6, col = i & (SMEM_K - 1);
        Ws[row * WS_STRIDE + col] = Wih[row * NH + REG_K + col];
    }
    const float bsum = b1[tid] + b2[tid];
    __syncthreads();

    const ulonglong2* wsl =
        reinterpret_cast<const ulonglong2*>(Ws + tid * WS_STRIDE);
    const int nrows = NB * NT;

    for (int r = blockIdx.x * 4; r < nrows; r += gridDim.x * 4) {
        #pragma unroll
        for (int rr = 0; rr < 4; rr++)
            rs[rr * NH + tid] = g_y[(size_t)(r + rr) * NH + tid];
        __syncthreads();

        const ulonglong2* r0 = reinterpret_cast<const ulonglong2*>(rs);
        const ulonglong2* r1 = r0 + NH / 4;
        const ulonglong2* r2 = r1 + NH / 4;
        const ulonglong2* r3 = r2 + NH / 4;
        unsigned long long a0 = 0, a1 = 0, a2 = 0, a3 = 0;

        #pragma unroll
        for (int j = 0; j < REG_K / 4; j++) {
            unsigned long long w0 = wreg2[2 * j], w1 = wreg2[2 * j + 1];
            ulonglong2 h0 = r0[j]; ffma2(a0, w0, h0.x); ffma2(a0, w1, h0.y);
            ulonglong2 h1 = r1[j]; ffma2(a1, w0, h1.x); ffma2(a1, w1, h1.y);
            ulonglong2 h2 = r2[j]; ffma2(a2, w0, h2.x); ffma2(a2, w1, h2.y);
            ulonglong2 h3 = r3[j]; ffma2(a3, w0, h3.x); ffma2(a3, w1, h3.y);
        }
        #pragma unroll
        for (int c = 0; c < SMEM_K / 4; c++) {
            ulonglong2 wv = wsl[c];
            ulonglong2 h0 = r0[REG_K / 4 + c]; ffma2(a0, wv.x, h0.x); ffma2(a0, wv.y, h0.y);
            ulonglong2 h1 = r1[REG_K / 4 + c]; ffma2(a1, wv.x, h1.x); ffma2(a1, wv.y, h1.y);
            ulonglong2 h2 = r2[REG_K / 4 + c]; ffma2(a2, wv.x, h2.x); ffma2(a2, wv.y, h2.y);
            ulonglong2 h3 = r3[REG_K / 4 + c]; ffma2(a3, wv.x, h3.x); ffma2(a3, wv.y, h3.y);
        }
        g_xp[(size_t)(r + 0) * NH + tid] = hsum2(a0) + bsum;
        g_xp[(size_t)(r + 1) * NH + tid] = hsum2(a1) + bsum;
        g_xp[(size_t)(r + 2) * NH + tid] = hsum2(a2) + bsum;
        g_xp[(size_t)(r + 3) * NH + tid] = hsum2(a3) + bsum;
        __syncthreads();
    }
}

__global__ void k_fc(const float* __restrict__ Wfc,
                     const float* __restrict__ bfc,
                     float* __restrict__ out) {
    int b = blockIdx.x, lane = threadIdx.x;
    const float* hrow = g_y + ((size_t)b * NT + (NT - 1)) * NH;
    float hv[8];
    #pragma unroll
    for (int k = 0; k < 8; k++) hv[k] = hrow[lane + 32 * k];
    #pragma unroll
    for (int c = 0; c < NC; c++) {
        float s = 0.0f;
        #pragma unroll
        for (int k = 0; k < 8; k++) s += hv[k] * Wfc[c * NH + lane + 32 * k];
        #pragma unroll
        for (int off = 16; off > 0; off >>= 1)
            s += __shfl_xor_sync(0xffffffffu, s, off);
        if (lane == 0) out[b * NC + c] = s + bfc[c];
    }
}

extern "C" void kernel_launch(void* const* d_in, const int* in_sizes, int n_in,
                              void* d_out, int out_size) {
    const float* x    = (const float*)d_in[0];
    const float* W0   = (const float*)d_in[1];
    const float* bi0  = (const float*)d_in[2];
    const float* Wih  = (const float*)d_in[3];
    const float* bih  = (const float*)d_in[4];
    const float* Whh  = (const float*)d_in[5];
    const float* bhh  = (const float*)d_in[6];
    const float* Wfc  = (const float*)d_in[7];
    const float* bfc  = (const float*)d_in[8];
    float* out = (float*)d_out;

    cudaFuncSetAttribute(k_scan, cudaFuncAttributeMaxDynamicSharedMemorySize,
                         SMEM_SCAN_BYTES);
    cudaFuncSetAttribute(k_proj, cudaFuncAttributeMaxDynamicSharedMemorySize,
                         SMEM_PROJ_BYTES);

    k_proj0<<<NB * NT, 256>>>(x, W0, bi0, bhh);
    for (int l = 0; l < NL; l++) {
        k_scan<<<NB, 256, SMEM_SCAN_BYTES>>>(Whh + (size_t)l * NH * NH);
        if (l + 1 < NL)
            k_proj<<<296, 256, SMEM_PROJ_BYTES>>>(Wih + (size_t)l * NH * NH,
                                                  bih + (size_t)l * NH,
                                                  bhh + (size_t)(l + 1) * NH);
    }
    k_fc<<<NB, 32>>>(Wfc, bfc, out);
}

// round 3
// speedup vs baseline: 1.0543x; 1.0543x over previous
#include <cuda_runtime.h>

#define NB 128
#define NT 784
#define NH 256
#define NL 20
#define NC 10
#define REG_K 192
#define SMEM_K 64
#define WS_STRIDE 68
#define TILE_R 8
#define PROJ_GRID 148

__device__ float g_xp[(size_t)NB * NT * NH];
__device__ float g_y [(size_t)NB * NT * NH];

static const int SMEM_SCAN_BYTES = (NH * WS_STRIDE + 2 * NH) * 4;
static const int SMEM_PROJ_BYTES = (NH * WS_STRIDE + 2 * TILE_R * NH) * 4;

__device__ __forceinline__ void ffma2(unsigned long long &d,
                                      unsigned long long a,
                                      unsigned long long b) {
    asm("fma.rn.f32x2 %0, %1, %2, %0;" : "+l"(d) : "l"(a), "l"(b));
}
__device__ __forceinline__ float hsum2(unsigned long long a) {
    unsigned int lo, hi;
    asm("mov.b64 {%0, %1}, %2;" : "=r"(lo), "=r"(hi) : "l"(a));
    return __uint_as_float(lo) + __uint_as_float(hi);
}

// layer-0 projection: I=1 -> xp = x*W_ih0[h] + b_ih0[h] + b_hh0[h]
__global__ void k_proj0(const float* __restrict__ x,
                        const float* __restrict__ w0,
                        const float* __restrict__ bi0,
                        const float* __restrict__ bh0) {
    int idx = blockIdx.x * 256 + threadIdx.x;
    int h  = idx & (NH - 1);
    int bt = idx >> 8;
    g_xp[idx] = x[bt] * w0[h] + bi0[h] + bh0[h];
}

// recurrence: one CTA per sample, h_t = relu(xp_t + W_hh h_{t-1})
__global__ __launch_bounds__(256, 1)
void k_scan(const float* __restrict__ Whh) {
    extern __shared__ float smem[];
    float* Ws   = smem;                   // [NH][WS_STRIDE]
    float* hbuf = smem + NH * WS_STRIDE;  // [2][NH]
    const int tid = threadIdx.x;
    const int b   = blockIdx.x;

    unsigned long long wreg2[REG_K / 2];
    {
        const ulonglong2* wrow =
            reinterpret_cast<const ulonglong2*>(Whh + (size_t)tid * NH);
        #pragma unroll
        for (int j = 0; j < REG_K / 4; j++) {
            ulonglong2 v = wrow[j];
            wreg2[2 * j] = v.x; wreg2[2 * j + 1] = v.y;
        }
    }
    for (int i = tid; i < NH * SMEM_K; i += 256) {
        int row = i >> 6, col = i & (SMEM_K - 1);
        Ws[row * WS_STRIDE + col] = Whh[row * NH + REG_K + col];
    }
    hbuf[tid] = 0.0f; hbuf[NH + tid] = 0.0f;
    __syncthreads();

    const float* xprow = g_xp + (size_t)b * NT * NH + tid;
    float*       yrow  = g_y  + (size_t)b * NT * NH + tid;
    const ulonglong2* wsl =
        reinterpret_cast<const ulonglong2*>(Ws + tid * WS_STRIDE);

    float xv = xprow[0];
    int cur = 0;
    for (int t = 0; t < NT; t++) {
        float xnext = (t + 1 < NT) ? xprow[(t + 1) * NH] : 0.0f;
        const ulonglong2* hc =
            reinterpret_cast<const ulonglong2*>(hbuf + cur * NH);
        unsigned long long a0 = 0, a1 = 0, a2 = 0, a3 = 0;
        #pragma unroll
        for (int j = 0; j < REG_K / 8; j++) {
            ulonglong2 h0 = hc[2 * j];
            ffma2(a0, wreg2[4 * j + 0], h0.x);
            ffma2(a1, wreg2[4 * j + 1], h0.y);
            ulonglong2 h1 = hc[2 * j + 1];
            ffma2(a2, wreg2[4 * j + 2], h1.x);
            ffma2(a3, wreg2[4 * j + 3], h1.y);
        }
        #pragma unroll
        for (int c = 0; c < SMEM_K / 4; c++) {
            ulonglong2 wv = wsl[c];
            ulonglong2 hv = hc[REG_K / 4 + c];
            ffma2(a0, wv.x, hv.x);
            ffma2(a1, wv.y, hv.y);
        }
        float s = (hsum2(a0) + hsum2(a1)) + (hsum2(a2) + hsum2(a3));
        float v = fmaxf(s + xv, 0.0f);
        int nxt = cur ^ 1;
        hbuf[nxt * NH + tid] = v;
        yrow[t * NH] = v;
        xv = xnext; cur = nxt;
        __syncthreads();
    }
}

// projection layers 1..L-1: xp[r,h] = Y[r,:].W_ih[h,:] + b_ih[h] + b_hh_next[h]
// 148 CTAs (one wave), 8-row tiles, double-buffered staging, 1 barrier/tile.
__global__ __launch_bounds__(256, 1)
void k_proj(const float* __restrict__ Wih,
            const float* __restrict__ b1,
            const float* __restrict__ b2) {
    extern __shared__ float smem[];
    float* Ws  = smem;                           // [NH][WS_STRIDE]
    float* buf = smem + NH * WS_STRIDE;          // [2][TILE_R*NH]
    const int tid = threadIdx.x;

    unsigned long long wreg2[REG_K / 2];
    {
        const ulonglong2* wrow =
            reinterpret_cast<const ulonglong2*>(Wih + (size_t)tid * NH);
        #pragma unroll
        for (int j = 0; j < REG_K / 4; j++) {
            ulonglong2 v = wrow[j];
            wreg2[2 * j] = v.x; wreg2[2 * j + 1] = v.y;
        }
    }
    for (int i = tid; i < NH * SMEM_K; i += 256) {
        int row = i >> 6, col = i & (SMEM_K - 1);
        Ws[row * WS_STRIDE + col] = Wih[row * NH + REG_K + col];
    }
    const float bsum = b1[tid] + b2[tid];
    __syncthreads();

    const ulonglong2* wsl =
        reinterpret_cast<const ulonglong2*>(Ws + tid * WS_STRIDE);
    const int ntiles = (NB * NT) / TILE_R;       // 12544

    // stage tile -> buf[sel]; 2048 floats = 512 float4; thread does 2
    auto stage = [&](int tile, int sel) {
        const float4* src = reinterpret_cast<const float4*>(
            g_y + (size_t)tile * TILE_R * NH);
        float4* dst = reinterpret_cast<float4*>(buf + sel * TILE_R * NH);
        dst[tid]       = src[tid];
        dst[tid + 256] = src[tid + 256];
    };

    int tile = blockIdx.x;
    if (tile < ntiles) stage(tile, 0);
    __syncthreads();

    int cur = 0;
    for (; tile < ntiles; tile += PROJ_GRID) {
        int nxt_tile = tile + PROJ_GRID;
        if (nxt_tile < ntiles) stage(nxt_tile, cur ^ 1);

        const float* base = buf + cur * TILE_R * NH;
        unsigned long long acc[TILE_R];
        #pragma unroll
        for (int rr = 0; rr < TILE_R; rr++) acc[rr] = 0ull;

        #pragma unroll
        for (int j = 0; j < REG_K / 4; j++) {
            unsigned long long w0 = wreg2[2 * j], w1 = wreg2[2 * j + 1];
            #pragma unroll
            for (int rr = 0; rr < TILE_R; rr++) {
                ulonglong2 h = reinterpret_cast<const ulonglong2*>(
                    base + rr * NH)[j];
                ffma2(acc[rr], w0, h.x);
                ffma2(acc[rr], w1, h.y);
            }
        }
        #pragma unroll
        for (int c = 0; c < SMEM_K / 4; c++) {
            ulonglong2 wv = wsl[c];
            #pragma unroll
            for (int rr = 0; rr < TILE_R; rr++) {
                ulonglong2 h = reinterpret_cast<const ulonglong2*>(
                    base + rr * NH)[REG_K / 4 + c];
                ffma2(acc[rr], wv.x, h.x);
                ffma2(acc[rr], wv.y, h.y);
            }
        }
        #pragma unroll
        for (int rr = 0; rr < TILE_R; rr++)
            g_xp[(size_t)(tile * TILE_R + rr) * NH + tid] =
                hsum2(acc[rr]) + bsum;

        cur ^= 1;
        __syncthreads();
    }
}

__global__ void k_fc(const float* __restrict__ Wfc,
                     const float* __restrict__ bfc,
                     float* __restrict__ out) {
    int b = blockIdx.x, lane = threadIdx.x;
    const float* hrow = g_y + ((size_t)b * NT + (NT - 1)) * NH;
    float hv[8];
    #pragma unroll
    for (int k = 0; k < 8; k++) hv[k] = hrow[lane + 32 * k];
    #pragma unroll
    for (int c = 0; c < NC; c++) {
        float s = 0.0f;
        #pragma unroll
        for (int k = 0; k < 8; k++) s += hv[k] * Wfc[c * NH + lane + 32 * k];
        #pragma unroll
        for (int off = 16; off > 0; off >>= 1)
            s += __shfl_xor_sync(0xffffffffu, s, off);
        if (lane == 0) out[b * NC + c] = s + bfc[c];
    }
}

extern "C" void kernel_launch(void* const* d_in, const int* in_sizes, int n_in,
                              void* d_out, int out_size) {
    const float* x    = (const float*)d_in[0];
    const float* W0   = (const float*)d_in[1];
    const float* bi0  = (const float*)d_in[2];
    const float* Wih  = (const float*)d_in[3];
    const float* bih  = (const float*)d_in[4];
    const float* Whh  = (const float*)d_in[5];
    const float* bhh  = (const float*)d_in[6];
    const float* Wfc  = (const float*)d_in[7];
    const float* bfc  = (const float*)d_in[8];
    float* out = (float*)d_out;

    cudaFuncSetAttribute(k_scan, cudaFuncAttributeMaxDynamicSharedMemorySize,
                         SMEM_SCAN_BYTES);
    cudaFuncSetAttribute(k_proj, cudaFuncAttributeMaxDynamicSharedMemorySize,
                         SMEM_PROJ_BYTES);

    k_proj0<<<NB * NT, 256>>>(x, W0, bi0, bhh);
    for (int l = 0; l < NL; l++) {
        k_scan<<<NB, 256, SMEM_SCAN_BYTES>>>(Whh + (size_t)l * NH * NH);
        if (l + 1 < NL)
            k_proj<<<PROJ_GRID, 256, SMEM_PROJ_BYTES>>>(
                Wih + (size_t)l * NH * NH,
                bih + (size_t)l * NH,
                bhh + (size_t)(l + 1) * NH);
    }
    k_fc<<<NB, 32>>>(Wfc, bfc, out);
}

// round 4
// speedup vs baseline: 1.2148x; 1.1523x over previous
#include <cuda_runtime.h>

#define NB 128
#define NT 784
#define NH 256
#define NL 20
#define NC 10
#define REG_K 192
#define SMEM_K 64
#define WS_STRIDE 68

__device__ float g_xp[(size_t)NB * NT * NH];
__device__ float g_y [(size_t)NB * NT * NH];

static const int SMEM_SCAN_BYTES = (NH * WS_STRIDE + 2 * NH) * 4;

__device__ __forceinline__ void ffma2(unsigned long long &d,
                                      unsigned long long a,
                                      unsigned long long b) {
    asm("fma.rn.f32x2 %0, %1, %2, %0;" : "+l"(d) : "l"(a), "l"(b));
}
__device__ __forceinline__ float hsum2(unsigned long long a) {
    unsigned int lo, hi;
    asm("mov.b64 {%0, %1}, %2;" : "=r"(lo), "=r"(hi) : "l"(a));
    return __uint_as_float(lo) + __uint_as_float(hi);
}
__device__ __forceinline__ unsigned long long packf2(float x, float y) {
    unsigned long long r;
    asm("mov.b64 %0, {%1, %2};" : "=l"(r) : "r"(__float_as_uint(x)),
                                   "r"(__float_as_uint(y)));
    return r;
}
__device__ __forceinline__ float2 unpackf2(unsigned long long a) {
    unsigned int lo, hi;
    asm("mov.b64 {%0, %1}, %2;" : "=r"(lo), "=r"(hi) : "l"(a));
    return make_float2(__uint_as_float(lo), __uint_as_float(hi));
}

// layer-0 projection: I=1 -> xp = x*W_ih0[h] + b_ih0[h] + b_hh0[h]
__global__ void k_proj0(const float* __restrict__ x,
                        const float* __restrict__ w0,
                        const float* __restrict__ bi0,
                        const float* __restrict__ bh0) {
    int idx = blockIdx.x * 256 + threadIdx.x;
    int h  = idx & (NH - 1);
    int bt = idx >> 8;
    g_xp[idx] = x[bt] * w0[h] + bi0[h] + bh0[h];
}

// recurrence: one CTA per sample, h_t = relu(xp_t + W_hh h_{t-1})
__global__ __launch_bounds__(256, 1)
void k_scan(const float* __restrict__ Whh) {
    extern __shared__ float smem[];
    float* Ws   = smem;                   // [NH][WS_STRIDE]
    float* hbuf = smem + NH * WS_STRIDE;  // [2][NH]
    const int tid = threadIdx.x;
    const int b   = blockIdx.x;

    unsigned long long wreg2[REG_K / 2];
    {
        const ulonglong2* wrow =
            reinterpret_cast<const ulonglong2*>(Whh + (size_t)tid * NH);
        #pragma unroll
        for (int j = 0; j < REG_K / 4; j++) {
            ulonglong2 v = wrow[j];
            wreg2[2 * j] = v.x; wreg2[2 * j + 1] = v.y;
        }
    }
    for (int i = tid; i < NH * SMEM_K; i += 256) {
        int row = i >> 6, col = i & (SMEM_K - 1);
        Ws[row * WS_STRIDE + col] = Whh[row * NH + REG_K + col];
    }
    hbuf[tid] = 0.0f; hbuf[NH + tid] = 0.0f;
    __syncthreads();

    const float* xprow = g_xp + (size_t)b * NT * NH + tid;
    float*       yrow  = g_y  + (size_t)b * NT * NH + tid;
    const ulonglong2* wsl =
        reinterpret_cast<const ulonglong2*>(Ws + tid * WS_STRIDE);

    float xv = xprow[0];
    int cur = 0;
    for (int t = 0; t < NT; t++) {
        float xnext = (t + 1 < NT) ? xprow[(t + 1) * NH] : 0.0f;
        const ulonglong2* hc =
            reinterpret_cast<const ulonglong2*>(hbuf + cur * NH);
        unsigned long long a0 = 0, a1 = 0, a2 = 0, a3 = 0;
        #pragma unroll
        for (int j = 0; j < REG_K / 8; j++) {
            ulonglong2 h0 = hc[2 * j];
            ffma2(a0, wreg2[4 * j + 0], h0.x);
            ffma2(a1, wreg2[4 * j + 1], h0.y);
            ulonglong2 h1 = hc[2 * j + 1];
            ffma2(a2, wreg2[4 * j + 2], h1.x);
            ffma2(a3, wreg2[4 * j + 3], h1.y);
        }
        #pragma unroll
        for (int c = 0; c < SMEM_K / 4; c++) {
            ulonglong2 wv = wsl[c];
            ulonglong2 hv = hc[REG_K / 4 + c];
            ffma2(a0, wv.x, hv.x);
            ffma2(a1, wv.y, hv.y);
        }
        float s = (hsum2(a0) + hsum2(a1)) + (hsum2(a2) + hsum2(a3));
        float v = fmaxf(s + xv, 0.0f);
        int nxt = cur ^ 1;
        hbuf[nxt * NH + tid] = v;
        yrow[t * NH] = v;
        xv = xnext; cur = nxt;
        __syncthreads();
    }
}

// -----------------------------------------------------------------------
// Register-tiled SGEMM projection, layers 1..L-1.
// XP[r,h] = sum_k Y[r,k]*Wih[h,k] + b1[h] + b2[h]
// CTA tile 128(rows) x 128(h), BK=16, double-buffered; thread -> 8x8 outputs.
// -----------------------------------------------------------------------
__global__ __launch_bounds__(256, 2)
void k_proj(const float* __restrict__ Wih,
            const float* __restrict__ b1,
            const float* __restrict__ b2) {
    __shared__ float As[2][16][128];
    __shared__ float Bs[2][16][128];

    const int tid = threadIdx.x;
    const int tx  = tid & 15;       // j-group
    const int ty  = tid >> 4;       // i-group
    const int bm  = blockIdx.x;     // 0..783
    const int bn  = blockIdx.y;     // 0..1

    const float* Ag = g_y + (size_t)bm * 128 * NH;
    const float* Bg = Wih + (size_t)bn * 128 * NH;

    // staging: 512 float4 per operand; thread does 2 each.
    const int idx0 = tid * 2;
    const int row0 = idx0 >> 2, cc0 = (idx0 & 3) * 4;
    const int idx1 = tid * 2 + 1;
    const int row1 = idx1 >> 2, cc1 = (idx1 & 3) * 4;

    #define STAGE(sel, ks)                                                  \
    {                                                                       \
        float4 a0v = *(const float4*)(Ag + row0 * NH + (ks) + cc0);         \
        float4 a1v = *(const float4*)(Ag + row1 * NH + (ks) + cc1);         \
        float4 b0v = *(const float4*)(Bg + row0 * NH + (ks) + cc0);         \
        float4 b1v = *(const float4*)(Bg + row1 * NH + (ks) + cc1);         \
        As[sel][cc0 + 0][row0] = a0v.x; As[sel][cc0 + 1][row0] = a0v.y;     \
        As[sel][cc0 + 2][row0] = a0v.z; As[sel][cc0 + 3][row0] = a0v.w;     \
        As[sel][cc1 + 0][row1] = a1v.x; As[sel][cc1 + 1][row1] = a1v.y;     \
        As[sel][cc1 + 2][row1] = a1v.z; As[sel][cc1 + 3][row1] = a1v.w;     \
        Bs[sel][cc0 + 0][row0] = b0v.x; Bs[sel][cc0 + 1][row0] = b0v.y;     \
        Bs[sel][cc0 + 2][row0] = b0v.z; Bs[sel][cc0 + 3][row0] = b0v.w;     \
        Bs[sel][cc1 + 0][row1] = b1v.x; Bs[sel][cc1 + 1][row1] = b1v.y;     \
        Bs[sel][cc1 + 2][row1] = b1v.z; Bs[sel][cc1 + 3][row1] = b1v.w;     \
    }

    unsigned long long acc[8][4];
    #pragma unroll
    for (int i = 0; i < 8; i++)
        #pragma unroll
        for (int j = 0; j < 4; j++) acc[i][j] = 0ull;

    STAGE(0, 0);
    __syncthreads();

    #pragma unroll 1
    for (int s = 0; s < 16; s++) {
        int sel = s & 1;
        if (s < 15) STAGE(sel ^ 1, (s + 1) * 16);

        #pragma unroll
        for (int k = 0; k < 16; k++) {
            float4 a0 = *(const float4*)&As[sel][k][ty * 4];
            float4 a1 = *(const float4*)&As[sel][k][64 + ty * 4];
            float4 bv0 = *(const float4*)&Bs[sel][k][tx * 4];
            float4 bv1 = *(const float4*)&Bs[sel][k][64 + tx * 4];
            unsigned long long bq0 = packf2(bv0.x, bv0.y);
            unsigned long long bq1 = packf2(bv0.z, bv0.w);
            unsigned long long bq2 = packf2(bv1.x, bv1.y);
            unsigned long long bq3 = packf2(bv1.z, bv1.w);
            float av[8] = {a0.x, a0.y, a0.z, a0.w, a1.x, a1.y, a1.z, a1.w};
            #pragma unroll
            for (int i = 0; i < 8; i++) {
                unsigned long long ad = packf2(av[i], av[i]);
                ffma2(acc[i][0], ad, bq0);
                ffma2(acc[i][1], ad, bq1);
                ffma2(acc[i][2], ad, bq2);
                ffma2(acc[i][3], ad, bq3);
            }
        }
        __syncthreads();
    }

    // epilogue: add bias, store
    const int jb0 = bn * 128 + tx * 4;
    const int jb1 = jb0 + 64;
    float4 bsA, bsB;
    {
        float4 x0 = *(const float4*)(b1 + jb0);
        float4 y0 = *(const float4*)(b2 + jb0);
        bsA = make_float4(x0.x + y0.x, x0.y + y0.y, x0.z + y0.z, x0.w + y0.w);
        float4 x1 = *(const float4*)(b1 + jb1);
        float4 y1 = *(const float4*)(b2 + jb1);
        bsB = make_float4(x1.x + y1.x, x1.y + y1.y, x1.z + y1.z, x1.w + y1.w);
    }
    #pragma unroll
    for (int i = 0; i < 8; i++) {
        int row = bm * 128 + ((i < 4) ? (ty * 4 + i) : (64 + ty * 4 + i - 4));
        float* orow = g_xp + (size_t)row * NH;
        float2 p0 = unpackf2(acc[i][0]);
        float2 p1 = unpackf2(acc[i][1]);
        float2 p2 = unpackf2(acc[i][2]);
        float2 p3 = unpackf2(acc[i][3]);
        float4 o0 = make_float4(p0.x + bsA.x, p0.y + bsA.y,
                                p1.x + bsA.z, p1.y + bsA.w);
        float4 o1 = make_float4(p2.x + bsB.x, p2.y + bsB.y,
                                p3.x + bsB.z, p3.y + bsB.w);
        *(float4*)(orow + jb0) = o0;
        *(float4*)(orow + jb1) = o1;
    }
    #undef STAGE
}

__global__ void k_fc(const float* __restrict__ Wfc,
                     const float* __restrict__ bfc,
                     float* __restrict__ out) {
    int b = blockIdx.x, lane = threadIdx.x;
    const float* hrow = g_y + ((size_t)b * NT + (NT - 1)) * NH;
    float hv[8];
    #pragma unroll
    for (int k = 0; k < 8; k++) hv[k] = hrow[lane + 32 * k];
    #pragma unroll
    for (int c = 0; c < NC; c++) {
        float s = 0.0f;
        #pragma unroll
        for (int k = 0; k < 8; k++) s += hv[k] * Wfc[c * NH + lane + 32 * k];
        #pragma unroll
        for (int off = 16; off > 0; off >>= 1)
            s += __shfl_xor_sync(0xffffffffu, s, off);
        if (lane == 0) out[b * NC + c] = s + bfc[c];
    }
}

extern "C" void kernel_launch(void* const* d_in, const int* in_sizes, int n_in,
                              void* d_out, int out_size) {
    const float* x    = (const float*)d_in[0];
    const float* W0   = (const float*)d_in[1];
    const float* bi0  = (const float*)d_in[2];
    const float* Wih  = (const float*)d_in[3];
    const float* bih  = (const float*)d_in[4];
    const float* Whh  = (const float*)d_in[5];
    const float* bhh  = (const float*)d_in[6];
    const float* Wfc  = (const float*)d_in[7];
    const float* bfc  = (const float*)d_in[8];
    float* out = (float*)d_out;

    cudaFuncSetAttribute(k_scan, cudaFuncAttributeMaxDynamicSharedMemorySize,
                         SMEM_SCAN_BYTES);

    k_proj0<<<NB * NT, 256>>>(x, W0, bi0, bhh);
    dim3 pg(NT, 2);   // 784 x 2 tiles of (128 rows x 128 cols)
    for (int l = 0; l < NL; l++) {
        k_scan<<<NB, 256, SMEM_SCAN_BYTES>>>(Whh + (size_t)l * NH * NH);
        if (l + 1 < NL)
            k_proj<<<pg, 256>>>(Wih + (size_t)l * NH * NH,
                                bih + (size_t)l * NH,
                                bhh + (size_t)(l + 1) * NH);
    }
    k_fc<<<NB, 32>>>(Wfc, bfc, out);
}